// round 2
// baseline (speedup 1.0000x reference)
#include <cuda_runtime.h>
#include <math.h>

#define BB   8
#define NN   1024
#define TT   32
#define FF   64
#define BT   (BB*TT)      // 256
#define TILE 64
#define PAD  68
#define ROWSTRIDE (TT*FF) // 2048 floats between consecutive n rows (fixed b,t)

#define SMEM_BYTES (4 * TILE * PAD * 4)

__global__ __launch_bounds__(256, 3)
void sgcn_kernel(const float* __restrict__ x,
                 const float* __restrict__ adj,
                 const float* __restrict__ theta,
                 float* __restrict__ out)
{
    extern __shared__ float sm[];
    float (*Qt)[PAD] = (float (*)[PAD])(sm);                  // Qt[k][n]   (Q transposed)
    float (*Kt)[PAD] = (float (*)[PAD])(sm + TILE * PAD);     // Kt[k][m]   (K transposed) / Wt[f][j]
    float (*Ks)[PAD] = (float (*)[PAD])(sm + 2 * TILE * PAD); // Ks[m][f]   (K row-major, V role)
    float (*Ps)[PAD] = (float (*)[PAD])(sm + 3 * TILE * PAD); // Ps[n][m]   (adj-weighted probs) / Os[n][f]

    const int tid = threadIdx.x;
    const int tx  = tid & 15;   // key/col group
    const int ty  = tid >> 4;   // query/row group
    const int bt  = blockIdx.y;
    const int b   = bt >> 5;    // bt / T   (T = 32)
    const int t   = bt & 31;    // bt % T
    const int n0  = blockIdx.x * TILE;

    // xt[bt, row, f] = x[((b*N + row)*T + t)*F + f]
    const size_t xbase = (size_t)b * NN * ROWSTRIDE + (size_t)t * FF;

    // ---------------- load Q tile (transposed into Qt[k][n]) ----------------
    {
        const int r = tid >> 2;   // local row 0..63
        const int q = tid & 3;    // quarter of the 64-float row
        const float4* src = (const float4*)(x + xbase + (size_t)(n0 + r) * ROWSTRIDE);
        #pragma unroll
        for (int v = 0; v < 4; ++v) {
            float4 d = src[q * 4 + v];
            int c = q * 16 + v * 4;
            Qt[c + 0][r] = d.x; Qt[c + 1][r] = d.y;
            Qt[c + 2][r] = d.z; Qt[c + 3][r] = d.w;
        }
    }

    float O[4][4];
    float mrun[4], Zrun[4];
    #pragma unroll
    for (int i = 0; i < 4; ++i) {
        mrun[i] = -INFINITY; Zrun[i] = 0.f;
        #pragma unroll
        for (int j = 0; j < 4; ++j) O[i][j] = 0.f;
    }
    const float scale = 0.125f;   // 1/sqrt(64)

    for (int m0 = 0; m0 < NN; m0 += TILE) {
        __syncthreads();   // prior V-GEMM (Ks/Ps reads) complete before reload
        // -------- load K tile: both row-major (Ks) and transposed (Kt) --------
        {
            const int r = tid >> 2;
            const int q = tid & 3;
            const float4* src = (const float4*)(x + xbase + (size_t)(m0 + r) * ROWSTRIDE);
            #pragma unroll
            for (int v = 0; v < 4; ++v) {
                float4 d = src[q * 4 + v];
                int c = q * 16 + v * 4;
                *(float4*)&Ks[r][c] = d;
                Kt[c + 0][r] = d.x; Kt[c + 1][r] = d.y;
                Kt[c + 2][r] = d.z; Kt[c + 3][r] = d.w;
            }
        }
        __syncthreads();

        // -------- S = (Q @ K^T) * scale --------
        float s[4][4];
        #pragma unroll
        for (int i = 0; i < 4; ++i)
            #pragma unroll
            for (int j = 0; j < 4; ++j) s[i][j] = 0.f;

        #pragma unroll 8
        for (int k = 0; k < FF; ++k) {
            float4 qf = *(const float4*)&Qt[k][ty * 4];
            float4 kf = *(const float4*)&Kt[k][tx * 4];
            float qa[4] = {qf.x, qf.y, qf.z, qf.w};
            float ka[4] = {kf.x, kf.y, kf.z, kf.w};
            #pragma unroll
            for (int i = 0; i < 4; ++i)
                #pragma unroll
                for (int j = 0; j < 4; ++j)
                    s[i][j] = fmaf(qa[i], ka[j], s[i][j]);
        }
        #pragma unroll
        for (int i = 0; i < 4; ++i)
            #pragma unroll
            for (int j = 0; j < 4; ++j) s[i][j] *= scale;

        // -------- online softmax bookkeeping (Z excludes adj; adj is post-softmax) --------
        #pragma unroll
        for (int i = 0; i < 4; ++i) {
            float tmax = fmaxf(fmaxf(s[i][0], s[i][1]), fmaxf(s[i][2], s[i][3]));
            #pragma unroll
            for (int off = 8; off > 0; off >>= 1)
                tmax = fmaxf(tmax, __shfl_xor_sync(0xffffffffu, tmax, off, 16));
            float mnew = fmaxf(mrun[i], tmax);
            float corr = __expf(mrun[i] - mnew);
            mrun[i] = mnew;
            float lsum = 0.f;
            #pragma unroll
            for (int j = 0; j < 4; ++j) {
                s[i][j] = __expf(s[i][j] - mnew);
                lsum += s[i][j];
            }
            #pragma unroll
            for (int off = 8; off > 0; off >>= 1)
                lsum += __shfl_xor_sync(0xffffffffu, lsum, off, 16);
            Zrun[i] = Zrun[i] * corr + lsum;
            #pragma unroll
            for (int j = 0; j < 4; ++j) O[i][j] *= corr;
        }

        // -------- apply adjacency mask, stage P into smem --------
        #pragma unroll
        for (int i = 0; i < 4; ++i) {
            float4 av = *(const float4*)(adj + (size_t)(n0 + ty * 4 + i) * NN + m0 + tx * 4);
            float4 pv;
            pv.x = s[i][0] * av.x; pv.y = s[i][1] * av.y;
            pv.z = s[i][2] * av.z; pv.w = s[i][3] * av.w;
            *(float4*)&Ps[ty * 4 + i][tx * 4] = pv;
        }
        __syncthreads();

        // -------- O += P_adj @ K  (V == K tile) --------
        #pragma unroll 8
        for (int m = 0; m < TILE; ++m) {
            float4 kf = *(const float4*)&Ks[m][tx * 4];
            float ka[4] = {kf.x, kf.y, kf.z, kf.w};
            #pragma unroll
            for (int i = 0; i < 4; ++i) {
                float p = Ps[ty * 4 + i][m];
                #pragma unroll
                for (int j = 0; j < 4; ++j)
                    O[i][j] = fmaf(p, ka[j], O[i][j]);
            }
        }
    }

    // -------- normalize: att = softmax * scale  =>  O *= scale / Z --------
    #pragma unroll
    for (int i = 0; i < 4; ++i) {
        float invz = scale / Zrun[i];
        #pragma unroll
        for (int j = 0; j < 4; ++j) O[i][j] *= invz;
    }

    __syncthreads();   // all loop-phase smem reads done; reuse Ps as Os, Kt as Wt

    // stage Os[n][f]
    #pragma unroll
    for (int i = 0; i < 4; ++i) {
        float4 ov = make_float4(O[i][0], O[i][1], O[i][2], O[i][3]);
        *(float4*)&Ps[ty * 4 + i][tx * 4] = ov;
    }
    // stage theta transposed: Wt[f][j] = theta_w[j, f]  (theta row-major (out,in))
    {
        const int r = tid >> 2;   // j (output feature)
        const int q = tid & 3;
        const float4* src = (const float4*)(theta + r * FF);
        #pragma unroll
        for (int v = 0; v < 4; ++v) {
            float4 d = src[q * 4 + v];
            int c = q * 16 + v * 4;   // f
            Kt[c + 0][r] = d.x; Kt[c + 1][r] = d.y;
            Kt[c + 2][r] = d.z; Kt[c + 3][r] = d.w;
        }
    }
    __syncthreads();

    // -------- out = relu(Os @ theta^T) --------
    float res[4][4];
    #pragma unroll
    for (int i = 0; i < 4; ++i)
        #pragma unroll
        for (int j = 0; j < 4; ++j) res[i][j] = 0.f;

    #pragma unroll 8
    for (int f = 0; f < FF; ++f) {
        float4 wf = *(const float4*)&Kt[f][tx * 4];
        float wa[4] = {wf.x, wf.y, wf.z, wf.w};
        #pragma unroll
        for (int i = 0; i < 4; ++i) {
            float o = Ps[ty * 4 + i][f];
            #pragma unroll
            for (int j = 0; j < 4; ++j)
                res[i][j] = fmaf(o, wa[j], res[i][j]);
        }
    }

    #pragma unroll
    for (int i = 0; i < 4; ++i) {
        const int n = n0 + ty * 4 + i;
        float4 r4;
        r4.x = fmaxf(res[i][0], 0.f); r4.y = fmaxf(res[i][1], 0.f);
        r4.z = fmaxf(res[i][2], 0.f); r4.w = fmaxf(res[i][3], 0.f);
        *(float4*)(out + xbase + (size_t)n * ROWSTRIDE + tx * 4) = r4;
    }
}

extern "C" void kernel_launch(void* const* d_in, const int* in_sizes, int n_in,
                              void* d_out, int out_size)
{
    // robust input identification by element count
    const float* x = nullptr; const float* adj = nullptr; const float* theta = nullptr;
    for (int i = 0; i < n_in; ++i) {
        if (in_sizes[i] == BB * NN * TT * FF)      x     = (const float*)d_in[i];
        else if (in_sizes[i] == NN * NN)           adj   = (const float*)d_in[i];
        else if (in_sizes[i] == FF * FF)           theta = (const float*)d_in[i];
    }
    float* out = (float*)d_out;

    cudaFuncSetAttribute(sgcn_kernel, cudaFuncAttributeMaxDynamicSharedMemorySize, SMEM_BYTES);

    dim3 grid(NN / TILE, BT);
    sgcn_kernel<<<grid, 256, SMEM_BYTES>>>(x, adj, theta, out);
}